// round 16
// baseline (speedup 1.0000x reference)
#include <cuda_runtime.h>
#include <cstdint>

// Problem constants
#define BATCH 64
#define TT    1000
#define NINP  64
#define HID   512
#define NACT  2

// Recurrence decomposition: 8 physical CTA-groups x 8 CTAs = 64 CTAs.
// Each CTA serves TWO logical batch-sets (same rank -> same weight slice).
#define GNC  8                    // CTAs per group (W_hh split by column)
#define NB   4                    // batches per logical set
#define JPC  64                   // HID / GNC columns per CTA
#define NSET 2                    // batch-sets per CTA (software pipeline)
#define NPG  8                    // physical CTA-groups
#define NLG  16                   // logical groups (NPG * NSET)
#define NTHR 512

// d_out layout: [out | hn_last | rnn_out]
#define HN_OFF  (BATCH * TT * NACT)
#define RNN_OFF (HN_OFF + BATCH * HID)

typedef unsigned long long u64;
typedef unsigned int u32;

// L2 exchange scratch: [lgroup 16][buf 2][src 8][j 64][b 4] floats = 256KB
#define EXCH_FLOATS (NLG * 2 * GNC * JPC * NB)
__device__ __align__(16) float g_exch[EXCH_FLOATS];

__device__ __forceinline__ int exch_idx(int lg, int buf, int src, int j) {
    return (((lg * 2 + buf) * GNC + src) * JPC + j) * NB;
}

// ---- packed f32x2 helpers ----
__device__ __forceinline__ u64 pk(float lo, float hi) {
    u64 r; asm("mov.b64 %0, {%1, %2};" : "=l"(r) : "f"(lo), "f"(hi)); return r;
}
__device__ __forceinline__ void upk(u64 v, float& lo, float& hi) {
    asm("mov.b64 {%0, %1}, %2;" : "=f"(lo), "=f"(hi) : "l"(v));
}
__device__ __forceinline__ u64 f2fma(u64 a, u64 b, u64 c) {
    u64 d; asm("fma.rn.f32x2 %0, %1, %2, %3;" : "=l"(d) : "l"(a), "l"(b), "l"(c));
    return d;
}

// .cg = L1-bypass, L2-coherent. Tearing/stale caught by per-word tag checks.
#define POLL_LD4(a, b, c, d, src) \
    asm volatile("ld.global.cg.v4.f32 {%0,%1,%2,%3}, [%4];" \
                 : "=f"(a), "=f"(b), "=f"(c), "=f"(d) : "l"(src) : "memory")

// ---------------------------------------------------------------------------
__global__ void k_clear() {   // reset exchange to invalid sentinel
    float4* p = reinterpret_cast<float4*>(g_exch);
    const int n4 = EXCH_FLOATS / 4;
    const float4 s = make_float4(-1.f, -1.f, -1.f, -1.f);
    for (int i = blockIdx.x * blockDim.x + threadIdx.x; i < n4;
         i += gridDim.x * blockDim.x)
        p[i] = s;
}

__global__ void k_nop() {}    // keeps ncu capture index aligned on k_rnn

// ---------------------------------------------------------------------------
// Kernel A: inp_proj = inp @ W_ih  (into rnn region, consumed in place)
// ---------------------------------------------------------------------------
__global__ void __launch_bounds__(512, 1) k_inproj(
    const float* __restrict__ inp, const float* __restrict__ W_ih,
    float* __restrict__ rnn)
{
    __shared__ alignas(16) float2 xsp[16][NINP];   // [row_pair][k]
    const int row0 = blockIdx.x * 32;
    for (int i = threadIdx.x; i < 32 * NINP; i += 512) {
        const int r = i >> 6, k = i & 63;
        ((float*)&xsp[r >> 1][k])[r & 1] = inp[(size_t)(row0 + r) * NINP + k];
    }
    __syncthreads();

    const int j = threadIdx.x;
    u64 acc[16];
#pragma unroll
    for (int r2 = 0; r2 < 16; r2++) acc[r2] = 0ull;

#pragma unroll 8
    for (int k = 0; k < NINP; k += 2) {
        const float wa = W_ih[k * HID + j];
        const float wb = W_ih[(k + 1) * HID + j];
        const u64 w0 = pk(wa, wa), w1 = pk(wb, wb);
#pragma unroll
        for (int r2 = 0; r2 < 16; r2++) {
            const ulonglong2 hv = *reinterpret_cast<const ulonglong2*>(&xsp[r2][k]);
            acc[r2] = f2fma(hv.x, w0, acc[r2]);
            acc[r2] = f2fma(hv.y, w1, acc[r2]);
        }
    }
#pragma unroll
    for (int r2 = 0; r2 < 16; r2++) {
        float lo, hi; upk(acc[r2], lo, hi);
        rnn[(size_t)(row0 + 2 * r2) * HID + j]     = lo;
        rnn[(size_t)(row0 + 2 * r2 + 1) * HID + j] = hi;
    }
}

// ---------------------------------------------------------------------------
// Kernel B: persistent recurrence, tagged L2 exchange, TWO interleaved
// batch-sets per CTA (set1 compute hides set0's L2 round trip and vice
// versa; same weight registers serve both sets). h_perm and red4 are
// PARITY DOUBLE-BUFFERED (R11 discipline): free-flowing groups may run up
// to one parity period ahead; poll-causality orders same-parity reuse.
// ---------------------------------------------------------------------------
__global__ void __launch_bounds__(NTHR, 1)
k_rnn(const float* __restrict__ hn, const float* __restrict__ W_hh,
      float* __restrict__ rnn, float* __restrict__ hn_last)
{
    __shared__ alignas(16) float h_perm[2][NSET][GNC * NB * JPC];  // 32KB
    __shared__ alignas(16) float red4[2][NSET][GNC][JPC][NB];      // 32KB

    const int me     = blockIdx.x;
    const int pg     = me >> 3;      // physical group 0..7
    const int rank_i = me & 7;

    const int tid = threadIdx.x;
    const int j   = tid & 63;        // column / word index
    const int kg  = tid >> 6;        // source block 0..7 (64 k each)
    const int col = rank_i * JPC + j;
    const bool is_epi = (kg == rank_i);

    // Weights: thread (kg, j) holds k in [kg*64, kg*64+64) for column col.
    u64 w2[32];
#pragma unroll
    for (int q = 0; q < 32; q++) {
        const int k = kg * 64 + 2 * q;
        w2[q] = pk(W_hh[(size_t)k * HID + col], W_hh[(size_t)(k + 1) * HID + col]);
    }

    // Prefill both sets' h_perm[0] with h0 (permuted)
    for (int i = tid; i < NSET * GNC * NB * JPC; i += NTHR) {
        const int s = i >> 11, r2 = i & 2047;
        const int r = r2 >> 8, b = (r2 >> 6) & 3, kk = r2 & 63;
        h_perm[0][s][r2] =
            hn[(size_t)((pg * 2 + s) * NB + b) * HID + r * JPC + kk];
    }
    __syncthreads();

    // epi thread state per set: running x pointer (time t) + prefetched x
    float* xq0 = (float*)(rnn + (size_t)(pg * 2 + 0) * NB * TT * HID + col);
    float* xq1 = (float*)(rnn + (size_t)(pg * 2 + 1) * NB * TT * HID + col);
    float xv0[NB], xv1[NB];
#pragma unroll
    for (int b = 0; b < NB; b++) {
        xv0[b] = is_epi ? __ldg(xq0 + (size_t)b * TT * HID) : 0.f;
        xv1[b] = is_epi ? __ldg(xq1 + (size_t)b * TT * HID) : 0.f;
    }

#pragma unroll 1
    for (int t = 0; t < TT; t++) {
        const int cur = t & 1, nxt = cur ^ 1, par = t & 1;
        const float lo   = 2.0f * (float)(t & 7);
        const float tagn = 2.0f * (float)((t + 1) & 7);
        const bool  last = (t == TT - 1);

        // one batch-set: poll -> FMA -> reduce -> (epi) epilogue + send
        auto do_set = [&](int s, int lg, float*& xq, float* xv, int bar_base) {
            // ---- Phase A: arrival (two-in-flight tagged poll) ----
            if (!is_epi && t > 0) {
                const float* src = g_exch + exch_idx(lg, cur, kg, j);
                float a0, a1, a2, a3, b0, b1, b2, b3;
                POLL_LD4(a0, a1, a2, a3, src);
                for (;;) {
                    POLL_LD4(b0, b1, b2, b3, src);
                    a0 -= lo; a1 -= lo; a2 -= lo; a3 -= lo;
                    if (a0 >= 0.f && a0 <= 1.f && a1 >= 0.f && a1 <= 1.f &&
                        a2 >= 0.f && a2 <= 1.f && a3 >= 0.f && a3 <= 1.f) break;
                    POLL_LD4(a0, a1, a2, a3, src);
                    b0 -= lo; b1 -= lo; b2 -= lo; b3 -= lo;
                    if (b0 >= 0.f && b0 <= 1.f && b1 >= 0.f && b1 <= 1.f &&
                        b2 >= 0.f && b2 <= 1.f && b3 >= 0.f && b3 <= 1.f) {
                        a0 = b0; a1 = b1; a2 = b2; a3 = b3; break;
                    }
                }
                float* hb = &h_perm[cur][s][kg * 256];
                hb[0 * 64 + j] = a0;
                hb[1 * 64 + j] = a1;
                hb[2 * 64 + j] = a2;
                hb[3 * 64 + j] = a3;
            }
            // group rendezvous: all 64 words of block kg staged
            asm volatile("bar.sync %0, 64;" :: "r"(kg + 1) : "memory");

            // ---- Phase B: FMA over our block for 4 batches ----
            const float* hc = &h_perm[cur][s][kg * 256];
            const ulonglong2* hp0 = (const ulonglong2*)(hc);
            const ulonglong2* hp1 = (const ulonglong2*)(hc + 64);
            const ulonglong2* hp2 = (const ulonglong2*)(hc + 128);
            const ulonglong2* hp3 = (const ulonglong2*)(hc + 192);
            u64 a0 = 0ull, a1 = 0ull, a2 = 0ull, a3 = 0ull;
#pragma unroll
            for (int q = 0; q < 16; q++) {
                const ulonglong2 v0 = hp0[q];
                a0 = f2fma(v0.x, w2[2*q], a0); a0 = f2fma(v0.y, w2[2*q+1], a0);
                const ulonglong2 v1 = hp1[q];
                a1 = f2fma(v1.x, w2[2*q], a1); a1 = f2fma(v1.y, w2[2*q+1], a1);
                const ulonglong2 v2 = hp2[q];
                a2 = f2fma(v2.x, w2[2*q], a2); a2 = f2fma(v2.y, w2[2*q+1], a2);
                const ulonglong2 v3 = hp3[q];
                a3 = f2fma(v3.x, w2[2*q], a3); a3 = f2fma(v3.y, w2[2*q+1], a3);
            }
            {
                float plo, phi, s0, s1, s2, s3;
                upk(a0, plo, phi); s0 = plo + phi;
                upk(a1, plo, phi); s1 = plo + phi;
                upk(a2, plo, phi); s2 = plo + phi;
                upk(a3, plo, phi); s3 = plo + phi;
                *(float4*)&red4[par][s][kg][j][0] = make_float4(s0, s1, s2, s3);
            }

            // ---- rendezvous on red4[par][s] (alternating ids by parity) ----
            if (is_epi) {
                asm volatile("bar.sync %0, %1;"
                             :: "r"(bar_base + par), "r"(NTHR) : "memory");

                // ---- Phase C: epilogue ----
                float v0 = xv[0], v1 = xv[1], v2 = xv[2], v3 = xv[3];
#pragma unroll
                for (int r = 0; r < GNC; r++) {
                    const float4 p = *(const float4*)&red4[par][s][r][j][0];
                    v0 += p.x; v1 += p.y; v2 += p.z; v3 += p.w;
                }
                float h4[NB];
                h4[0] = 1.f / (1.f + __expf(-v0));
                h4[1] = 1.f / (1.f + __expf(-v1));
                h4[2] = 1.f / (1.f + __expf(-v2));
                h4[3] = 1.f / (1.f + __expf(-v3));

                if (!last) {
                    // SEND FIRST (inter-CTA critical path)
                    float* dst = g_exch + exch_idx(lg, nxt, rank_i, j);
                    asm volatile("st.global.cg.v4.f32 [%0], {%1,%2,%3,%4};"
                                 :: "l"(dst),
                                    "f"(h4[0] + tagn), "f"(h4[1] + tagn),
                                    "f"(h4[2] + tagn), "f"(h4[3] + tagn)
                                 : "memory");
                    // local staging for next step (next parity buffer)
                    float* hb = &h_perm[nxt][s][rank_i * 256];
                    hb[0 * 64 + j] = h4[0];
                    hb[1 * 64 + j] = h4[1];
                    hb[2 * 64 + j] = h4[2];
                    hb[3 * 64 + j] = h4[3];
                    // off critical path: outputs + next x prefetch
#pragma unroll
                    for (int b = 0; b < NB; b++) {
                        xq[(size_t)b * TT * HID] = h4[b];
                        xv[b] = __ldg(xq + (size_t)b * TT * HID + HID);
                    }
                    xq += HID;
                } else {
#pragma unroll
                    for (int b = 0; b < NB; b++) {
                        xq[(size_t)b * TT * HID] = h4[b];
                        hn_last[(size_t)(lg * NB + b) * HID + col] = h4[b];
                    }
                }
            } else {
                asm volatile("bar.arrive %0, %1;"
                             :: "r"(bar_base + par), "r"(NTHR) : "memory");
            }
        };

        do_set(0, pg * 2 + 0, xq0, xv0, 9);    // bars 9/10
        do_set(1, pg * 2 + 1, xq1, xv1, 11);   // bars 11/12
    }
}

// ---------------------------------------------------------------------------
// Kernel C: out = sigmoid(rnn_out @ W_fc + b_fc). One warp per (b,t) row.
// ---------------------------------------------------------------------------
__global__ void __launch_bounds__(256, 8) k_fc(
    const float* __restrict__ rnn, const float* __restrict__ W_fc,
    const float* __restrict__ b_fc, float* __restrict__ out)
{
    __shared__ float wfc[HID * NACT];
    for (int i = threadIdx.x; i < HID * NACT; i += 256) wfc[i] = W_fc[i];
    __syncthreads();

    const int warp = threadIdx.x >> 5, lane = threadIdx.x & 31;
    const size_t row = (size_t)blockIdx.x * 8 + warp;
    const float4* rp = reinterpret_cast<const float4*>(rnn + row * HID);

    float a0 = 0.f, a1 = 0.f;
#pragma unroll
    for (int i = 0; i < 4; i++) {
        const float4 vv = rp[lane + 32 * i];
        const int k = (lane + 32 * i) * 4;
        a0 = fmaf(vv.x, wfc[(k + 0) * 2 + 0], a0);
        a1 = fmaf(vv.x, wfc[(k + 0) * 2 + 1], a1);
        a0 = fmaf(vv.y, wfc[(k + 1) * 2 + 0], a0);
        a1 = fmaf(vv.y, wfc[(k + 1) * 2 + 1], a1);
        a0 = fmaf(vv.z, wfc[(k + 2) * 2 + 0], a0);
        a1 = fmaf(vv.z, wfc[(k + 2) * 2 + 1], a1);
        a0 = fmaf(vv.w, wfc[(k + 3) * 2 + 0], a0);
        a1 = fmaf(vv.w, wfc[(k + 3) * 2 + 1], a1);
    }
#pragma unroll
    for (int off = 16; off > 0; off >>= 1) {
        a0 += __shfl_xor_sync(0xffffffffu, a0, off);
        a1 += __shfl_xor_sync(0xffffffffu, a1, off);
    }
    if (lane == 0) {
        out[row * NACT + 0] = 1.f / (1.f + __expf(-(a0 + b_fc[0])));
        out[row * NACT + 1] = 1.f / (1.f + __expf(-(a1 + b_fc[1])));
    }
}

// ---------------------------------------------------------------------------
extern "C" void kernel_launch(void* const* d_in, const int* in_sizes, int n_in,
                              void* d_out, int out_size)
{
    const float* inp  = (const float*)d_in[0];
    const float* hn   = (const float*)d_in[1];
    const float* W_hh = (const float*)d_in[2];
    const float* W_ih = (const float*)d_in[3];
    const float* W_fc = (const float*)d_in[4];
    const float* b_fc = (const float*)d_in[5];

    float* out = (float*)d_out;
    float* hnl = out + HN_OFF;
    float* rnn = out + RNN_OFF;

    k_clear<<<64, 256>>>();                               // reset exchange tags
    k_inproj<<<(BATCH * TT) / 32, 512>>>(inp, W_ih, rnn);
    k_nop<<<1, 32>>>();                                   // ncu index alignment
    k_rnn<<<NPG * GNC, NTHR>>>(hn, W_hh, rnn, hnl);
    k_fc<<<(BATCH * TT) / 8, 256>>>(rnn, W_fc, b_fc, out);
}

// round 17
// speedup vs baseline: 1.8218x; 1.8218x over previous
#include <cuda_runtime.h>
#include <cstdint>

// Problem constants
#define BATCH 64
#define TT    1000
#define NINP  64
#define HID   512
#define NACT  2

// Recurrence decomposition: 16 groups x 8 CTAs (no HW clusters)
#define GNC  8                    // CTAs per group (W_hh split by column)
#define NB   4                    // batches per group
#define JPC  64                   // HID / GNC columns per CTA
#define NGROUP (BATCH / NB)       // 16 groups -> 128 CTAs
#define NTHR 512

// d_out layout: [out | hn_last | rnn_out]
#define HN_OFF  (BATCH * TT * NACT)
#define RNN_OFF (HN_OFF + BATCH * HID)

typedef unsigned long long u64;
typedef unsigned int u32;

// L2 exchange scratch: [group 16][buf 2][src 8][j 64][b 4] floats = 256KB
#define EXCH_FLOATS (NGROUP * 2 * GNC * JPC * NB)
__device__ __align__(16) float g_exch[EXCH_FLOATS];

__device__ __forceinline__ int exch_idx(int group, int buf, int src, int j) {
    return (((group * 2 + buf) * GNC + src) * JPC + j) * NB;
}

// ---- packed f32x2 helpers ----
__device__ __forceinline__ u64 pk(float lo, float hi) {
    u64 r; asm("mov.b64 %0, {%1, %2};" : "=l"(r) : "f"(lo), "f"(hi)); return r;
}
__device__ __forceinline__ void upk(u64 v, float& lo, float& hi) {
    asm("mov.b64 {%0, %1}, %2;" : "=f"(lo), "=f"(hi) : "l"(v));
}
__device__ __forceinline__ u64 f2fma(u64 a, u64 b, u64 c) {
    u64 d; asm("fma.rn.f32x2 %0, %1, %2, %3;" : "=l"(d) : "l"(a), "l"(b), "l"(c));
    return d;
}

// .cg = L1-bypass, L2-coherent. Tearing/stale caught by per-word tag checks.
#define POLL_LD2(a, b, src) \
    asm volatile("ld.global.cg.v2.f32 {%0,%1}, [%2];" \
                 : "=f"(a), "=f"(b) : "l"(src) : "memory")

// ---------------------------------------------------------------------------
__global__ void k_clear() {   // reset exchange to invalid sentinel
    float4* p = reinterpret_cast<float4*>(g_exch);
    const int n4 = EXCH_FLOATS / 4;
    const float4 s = make_float4(-1.f, -1.f, -1.f, -1.f);
    for (int i = blockIdx.x * blockDim.x + threadIdx.x; i < n4;
         i += gridDim.x * blockDim.x)
        p[i] = s;
}

__global__ void k_nop() {}    // keeps ncu capture index aligned on k_rnn

// ---------------------------------------------------------------------------
// Kernel A: inp_proj = inp @ W_ih  (into rnn region, consumed in place)
// ---------------------------------------------------------------------------
__global__ void __launch_bounds__(512, 1) k_inproj(
    const float* __restrict__ inp, const float* __restrict__ W_ih,
    float* __restrict__ rnn)
{
    __shared__ alignas(16) float2 xsp[16][NINP];   // [row_pair][k]
    const int row0 = blockIdx.x * 32;
    for (int i = threadIdx.x; i < 32 * NINP; i += 512) {
        const int r = i >> 6, k = i & 63;
        ((float*)&xsp[r >> 1][k])[r & 1] = inp[(size_t)(row0 + r) * NINP + k];
    }
    __syncthreads();

    const int j = threadIdx.x;
    u64 acc[16];
#pragma unroll
    for (int r2 = 0; r2 < 16; r2++) acc[r2] = 0ull;

#pragma unroll 8
    for (int k = 0; k < NINP; k += 2) {
        const float wa = W_ih[k * HID + j];
        const float wb = W_ih[(k + 1) * HID + j];
        const u64 w0 = pk(wa, wa), w1 = pk(wb, wb);
#pragma unroll
        for (int r2 = 0; r2 < 16; r2++) {
            const ulonglong2 hv = *reinterpret_cast<const ulonglong2*>(&xsp[r2][k]);
            acc[r2] = f2fma(hv.x, w0, acc[r2]);
            acc[r2] = f2fma(hv.y, w1, acc[r2]);
        }
    }
#pragma unroll
    for (int r2 = 0; r2 < 16; r2++) {
        float lo, hi; upk(acc[r2], lo, hi);
        rnn[(size_t)(row0 + 2 * r2) * HID + j]     = lo;
        rnn[(size_t)(row0 + 2 * r2 + 1) * HID + j] = hi;
    }
}

// ---------------------------------------------------------------------------
// Kernel B: persistent recurrence, tagged L2 exchange (R11 protocol), step
// split into TWO batch-halves ({0,1} then {2,3}). Half-0's epi->send->L2->
// poll chain hides under half-1's FMA and vice versa across the step
// boundary. Parity double-buffers + alternating bar ids per half (R11
// induction re-derived per half).
// ---------------------------------------------------------------------------
__global__ void __launch_bounds__(NTHR, 1)
k_rnn(const float* __restrict__ hn, const float* __restrict__ W_hh,
      float* __restrict__ rnn, float* __restrict__ hn_last)
{
    __shared__ alignas(16) float h_perm[2][GNC * NB * JPC];  // 2 x 8KB
    __shared__ alignas(16) float red4[2][GNC][JPC][NB];      // 2 x 8KB, b minor

    const int me     = blockIdx.x;
    const int group  = me >> 3;
    const int rank_i = me & 7;
    const int b_base = group * NB;

    const int tid = threadIdx.x;
    const int j   = tid & 63;     // column / word index
    const int kg  = tid >> 6;     // source block 0..7 (64 k each)
    const int col = rank_i * JPC + j;
    const bool is_epi = (kg == rank_i);

    // Weights: thread (kg, j) holds k in [kg*64, kg*64+64) for column col
    u64 w2[32];
#pragma unroll
    for (int q = 0; q < 32; q++) {
        const int k = kg * 64 + 2 * q;
        w2[q] = pk(W_hh[(size_t)k * HID + col], W_hh[(size_t)(k + 1) * HID + col]);
    }

    // Prefill h_perm[0] with h0 (permuted)
    for (int i = tid; i < GNC * NB * JPC; i += NTHR) {
        const int r = i >> 8, b = (i >> 6) & 3, kk = i & 63;
        h_perm[0][i] = hn[(size_t)(b_base + b) * HID + r * JPC + kk];
    }
    __syncthreads();

    // epi thread state: x pointers + prefetched x values (4 batches)
    float* xp[NB];
    float xv[NB];
#pragma unroll
    for (int b = 0; b < NB; b++) {
        xp[b] = (float*)(rnn + (size_t)(b_base + b) * TT * HID + col);
        xv[b] = is_epi ? __ldg(xp[b]) : 0.f;
    }

#pragma unroll 1
    for (int t = 0; t < TT; t++) {
        const int cur = t & 1, nxt = cur ^ 1, par = t & 1;
        const float lo   = 2.0f * (float)(t & 7);
        const float tagn = 2.0f * (float)((t + 1) & 7);
        const bool  last = (t == TT - 1);

#pragma unroll
        for (int half = 0; half < 2; half++) {
            const int b0 = half * 2, b1 = half * 2 + 1;
            const int rbar = (half ? 11 : 9) + par;   // 9/10 or 11/12

            // ---- Phase A: arrival (two-in-flight tagged v2 poll) ----
            if (!is_epi && t > 0) {
                const float* src =
                    g_exch + exch_idx(group, cur, kg, j) + half * 2;
                float a0, a1, c0, c1;
                POLL_LD2(a0, a1, src);
                for (;;) {
                    POLL_LD2(c0, c1, src);         // in flight while checking A
                    a0 -= lo; a1 -= lo;
                    if (a0 >= 0.f && a0 <= 1.f && a1 >= 0.f && a1 <= 1.f) break;
                    POLL_LD2(a0, a1, src);         // in flight while checking C
                    c0 -= lo; c1 -= lo;
                    if (c0 >= 0.f && c0 <= 1.f && c1 >= 0.f && c1 <= 1.f) {
                        a0 = c0; a1 = c1; break;
                    }
                }
                float* hb = &h_perm[cur][kg * 256];
                hb[b0 * 64 + j] = a0;
                hb[b1 * 64 + j] = a1;
            }
            // group rendezvous: this half's rows of block kg staged
            asm volatile("bar.sync %0, 64;" :: "r"(kg + 1) : "memory");

            // ---- Phase B: FMA over our block for this half's 2 batches ----
            const float* hc = &h_perm[cur][kg * 256];
            const ulonglong2* hq0 = (const ulonglong2*)(hc + b0 * 64);
            const ulonglong2* hq1 = (const ulonglong2*)(hc + b1 * 64);
            u64 a0 = 0ull, a1 = 0ull;
#pragma unroll
            for (int q = 0; q < 16; q++) {
                const ulonglong2 v0 = hq0[q];
                a0 = f2fma(v0.x, w2[2*q], a0); a0 = f2fma(v0.y, w2[2*q+1], a0);
                const ulonglong2 v1 = hq1[q];
                a1 = f2fma(v1.x, w2[2*q], a1); a1 = f2fma(v1.y, w2[2*q+1], a1);
            }
            {
                float plo, phi, s0, s1;
                upk(a0, plo, phi); s0 = plo + phi;
                upk(a1, plo, phi); s1 = plo + phi;
                *(float2*)&red4[par][kg][j][b0] = make_float2(s0, s1);
            }

            // ---- rendezvous on this half's red (alternating ids) ----
            if (is_epi) {
                asm volatile("bar.sync %0, %1;" :: "r"(rbar), "r"(NTHR) : "memory");

                // ---- Phase C: epilogue for this half ----
                float v0 = xv[b0], v1 = xv[b1];
#pragma unroll
                for (int r = 0; r < GNC; r++) {
                    const float2 p = *(const float2*)&red4[par][r][j][b0];
                    v0 += p.x; v1 += p.y;
                }
                const float h0 = 1.f / (1.f + __expf(-v0));
                const float h1 = 1.f / (1.f + __expf(-v1));

                if (!last) {
                    // SEND FIRST (inter-CTA critical path)
                    float* dst =
                        g_exch + exch_idx(group, nxt, rank_i, j) + half * 2;
                    asm volatile("st.global.cg.v2.f32 [%0], {%1,%2};"
                                 :: "l"(dst), "f"(h0 + tagn), "f"(h1 + tagn)
                                 : "memory");
                    // local staging for next step (next parity buffer)
                    float* hb = &h_perm[nxt][rank_i * 256];
                    hb[b0 * 64 + j] = h0;
                    hb[b1 * 64 + j] = h1;
                    // off critical path: outputs + next x prefetch
                    xp[b0][(size_t)t * HID] = h0;
                    xp[b1][(size_t)t * HID] = h1;
                    xv[b0] = __ldg(xp[b0] + (size_t)(t + 1) * HID);
                    xv[b1] = __ldg(xp[b1] + (size_t)(t + 1) * HID);
                } else {
                    xp[b0][(size_t)t * HID] = h0;
                    xp[b1][(size_t)t * HID] = h1;
                    hn_last[(size_t)(b_base + b0) * HID + col] = h0;
                    hn_last[(size_t)(b_base + b1) * HID + col] = h1;
                }
            } else {
                asm volatile("bar.arrive %0, %1;" :: "r"(rbar), "r"(NTHR) : "memory");
            }
        }
    }
}

// ---------------------------------------------------------------------------
// Kernel C: out = sigmoid(rnn_out @ W_fc + b_fc). One warp per (b,t) row.
// ---------------------------------------------------------------------------
__global__ void __launch_bounds__(256, 8) k_fc(
    const float* __restrict__ rnn, const float* __restrict__ W_fc,
    const float* __restrict__ b_fc, float* __restrict__ out)
{
    __shared__ float wfc[HID * NACT];
    for (int i = threadIdx.x; i < HID * NACT; i += 256) wfc[i] = W_fc[i];
    __syncthreads();

    const int warp = threadIdx.x >> 5, lane = threadIdx.x & 31;
    const size_t row = (size_t)blockIdx.x * 8 + warp;
    const float4* rp = reinterpret_cast<const float4*>(rnn + row * HID);

    float a0 = 0.f, a1 = 0.f;
#pragma unroll
    for (int i = 0; i < 4; i++) {
        const float4 vv = rp[lane + 32 * i];
        const int k = (lane + 32 * i) * 4;
        a0 = fmaf(vv.x, wfc[(k + 0) * 2 + 0], a0);
        a1 = fmaf(vv.x, wfc[(k + 0) * 2 + 1], a1);
        a0 = fmaf(vv.y, wfc[(k + 1) * 2 + 0], a0);
        a1 = fmaf(vv.y, wfc[(k + 1) * 2 + 1], a1);
        a0 = fmaf(vv.z, wfc[(k + 2) * 2 + 0], a0);
        a1 = fmaf(vv.z, wfc[(k + 2) * 2 + 1], a1);
        a0 = fmaf(vv.w, wfc[(k + 3) * 2 + 0], a0);
        a1 = fmaf(vv.w, wfc[(k + 3) * 2 + 1], a1);
    }
#pragma unroll
    for (int off = 16; off > 0; off >>= 1) {
        a0 += __shfl_xor_sync(0xffffffffu, a0, off);
        a1 += __shfl_xor_sync(0xffffffffu, a1, off);
    }
    if (lane == 0) {
        out[row * NACT + 0] = 1.f / (1.f + __expf(-(a0 + b_fc[0])));
        out[row * NACT + 1] = 1.f / (1.f + __expf(-(a1 + b_fc[1])));
    }
}

// ---------------------------------------------------------------------------
extern "C" void kernel_launch(void* const* d_in, const int* in_sizes, int n_in,
                              void* d_out, int out_size)
{
    const float* inp  = (const float*)d_in[0];
    const float* hn   = (const float*)d_in[1];
    const float* W_hh = (const float*)d_in[2];
    const float* W_ih = (const float*)d_in[3];
    const float* W_fc = (const float*)d_in[4];
    const float* b_fc = (const float*)d_in[5];

    float* out = (float*)d_out;
    float* hnl = out + HN_OFF;
    float* rnn = out + RNN_OFF;

    k_clear<<<64, 256>>>();                               // reset exchange tags
    k_inproj<<<(BATCH * TT) / 32, 512>>>(inp, W_ih, rnn);
    k_nop<<<1, 32>>>();                                   // ncu index alignment
    k_rnn<<<NGROUP * GNC, NTHR>>>(hn, W_hh, rnn, hnl);
    k_fc<<<(BATCH * TT) / 8, 256>>>(rnn, W_fc, b_fc, out);
}